// round 7
// baseline (speedup 1.0000x reference)
#include <cuda_runtime.h>
#include <cuda_bf16.h>
#include <cstdint>

#define B_ 2
#define S_ 2048
#define D_ 256
#define H_ 8
#define BR 64
#define BC 64
#define LOG2E 1.44269504f

// Scratch (no allocations allowed -> static device globals)
__device__ float g_Q[(size_t)B_ * H_ * S_ * D_];   // tf32-rounded, pre-scaled by 1/16
__device__ float g_K[(size_t)B_ * H_ * S_ * D_];   // tf32-rounded
__device__ float g_V[(size_t)B_ * H_ * S_ * D_];   // tf32-rounded
__device__ float g_O[(size_t)B_ * S_ * H_ * D_];   // raw fp32 [B,S,H,D]

// round-to-nearest tf32 (unbiased)
__device__ __forceinline__ float f2tf32(float x) {
    uint32_t r;
    asm("cvt.rna.tf32.f32 %0, %1;" : "=r"(r) : "f"(x));
    return __uint_as_float(r);
}

__device__ __forceinline__ void mma_tf32(float* c, const uint32_t* a, const uint32_t* b) {
    asm volatile(
        "mma.sync.aligned.m16n8k8.row.col.f32.tf32.tf32.f32 "
        "{%0,%1,%2,%3}, {%4,%5,%6,%7}, {%8,%9}, {%0,%1,%2,%3};"
        : "+f"(c[0]), "+f"(c[1]), "+f"(c[2]), "+f"(c[3])
        : "r"(a[0]), "r"(a[1]), "r"(a[2]), "r"(a[3]), "r"(b[0]), "r"(b[1]));
}

__device__ __forceinline__ void cpa16(uint32_t dst, const void* src) {
    asm volatile("cp.async.cg.shared.global [%0], [%1], 16;" :: "r"(dst), "l"(src));
}
__device__ __forceinline__ void cpa_commit() { asm volatile("cp.async.commit_group;"); }

// ===========================================================================
//                    FLASH ATTENTION (qk + softmax + pv fused)
// ===========================================================================
// smem float offsets
#define OFF_Q 0        // [4][64][64]  Q chunks, A-swizzle
#define OFF_K 16384    // [4][64][64]  K chunks, A-swizzle
#define OFF_V 32768    // [4][64][64]  V chunks, V-swizzle
#define OFF_P 49152    // [64][64]     P tile, A-swizzle
#define OFF_M 53248    // [64] running row max
#define OFF_L 53312    // [64] running row sum
#define OFF_AL 53376   // [64] alpha
#define OFF_BUF 53440  // [4][64] cross-warp partials
#define SMEM_FLOATS 53696
#define FLASH_SMEM_BYTES (SMEM_FLOATS * 4)

// A/B-frag swizzle (rows keyed by row&7): per-instruction banks = c ^ 4g + const -> bijective
__device__ __forceinline__ int aidx(int r, int c) { return r * 64 + (c ^ ((r & 7) << 2)); }
// V NN-frag swizzle (rows keyed by row&3): banks = g + 8*(ni^c) -> bijective
__device__ __forceinline__ int vidx(int r, int c) { return r * 64 + (c ^ ((r & 3) << 3)); }

// load a [64 x 256] fp32 tile as 4 chunks of [64][64] into smem with swizzle
__device__ __forceinline__ void load_tile_a(uint32_t sbase, const float* g, int row0, int t) {
    #pragma unroll
    for (int i = 0; i < 16; i++) {
        int id = t + (i << 8);
        int ch = id >> 10, r = (id >> 4) & 63, w = id & 15;
        int dst = (ch << 12) + r * 64 + ((w << 2) ^ ((r & 7) << 2));
        cpa16(sbase + dst * 4, g + (size_t)(row0 + r) * D_ + (ch << 6) + (w << 2));
    }
}
__device__ __forceinline__ void load_tile_v(uint32_t sbase, const float* g, int row0, int t) {
    #pragma unroll
    for (int i = 0; i < 16; i++) {
        int id = t + (i << 8);
        int ch = id >> 10, r = (id >> 4) & 63, w = id & 15;
        int dst = (ch << 12) + r * 64 + ((w << 2) ^ ((r & 3) << 3));
        cpa16(sbase + dst * 4, g + (size_t)(row0 + r) * D_ + (ch << 6) + (w << 2));
    }
}

__global__ __launch_bounds__(256, 1) void flash_kernel()
{
    extern __shared__ float smf[];
    float* sQ  = smf + OFF_Q;
    float* sK  = smf + OFF_K;
    float* sV  = smf + OFF_V;
    float* sP  = smf + OFF_P;
    float* sM  = smf + OFF_M;
    float* sL  = smf + OFF_L;
    float* sAl = smf + OFF_AL;
    float* sBf = smf + OFF_BUF;

    const int t    = threadIdx.x;
    const int lane = t & 31;
    const int wid  = t >> 5;
    const int g    = lane >> 2;
    const int c    = lane & 3;
    const int wm   = wid >> 2;     // QK role: 2 m-warps
    const int wn   = wid & 3;      // QK role: 4 n-warps
    const int bh   = blockIdx.y;
    const int qt   = (int)gridDim.x - 1 - (int)blockIdx.x;   // heavy tiles first
    const int q0   = qt * BR;

    const float* Qg = g_Q + (size_t)bh * S_ * D_;
    const float* Kg = g_K + (size_t)bh * S_ * D_;
    const float* Vg = g_V + (size_t)bh * S_ * D_;

    const uint32_t sQs = (uint32_t)__cvta_generic_to_shared(sQ);
    const uint32_t sKs = (uint32_t)__cvta_generic_to_shared(sK);
    const uint32_t sVs = (uint32_t)__cvta_generic_to_shared(sV);

    if (t < 64) { sM[t] = -1e30f; sL[t] = 0.0f; }

    // prologue: group1 = Q + K(0); group2 = V(0)
    load_tile_a(sQs, Qg, q0, t);
    load_tile_a(sKs, Kg, 0, t);
    cpa_commit();
    load_tile_v(sVs, Vg, 0, t);
    cpa_commit();

    float oacc[4][4][4] = {};   // [m-atom][n-atom][frag], rows mi*16+g(+8), dcols wid*32+ni*8+2c(+1)

    for (int j = 0; j <= qt; j++) {
        const bool diag = (j == qt);

        // K(j)+Q ready (leave V(j) in flight)
        asm volatile("cp.async.wait_group 1;");
        __syncthreads();

        // ---------------- QK: S[64x64], warp tile 32x16 ----------------
        float sacc[2][2][4] = {};
        #pragma unroll
        for (int ch = 0; ch < 4; ch++) {
            const float* qch = sQ + (ch << 12);
            const float* kch = sK + (ch << 12);
            #pragma unroll
            for (int kt = 0; kt < 8; kt++) {
                const int kk = (kt << 3) + c;
                uint32_t a[2][4], b[2][2];
                #pragma unroll
                for (int mi = 0; mi < 2; mi++) {
                    const int r = wm * 32 + mi * 16 + g;
                    a[mi][0] = __float_as_uint(qch[aidx(r,     kk)]);
                    a[mi][1] = __float_as_uint(qch[aidx(r + 8, kk)]);
                    a[mi][2] = __float_as_uint(qch[aidx(r,     kk + 4)]);
                    a[mi][3] = __float_as_uint(qch[aidx(r + 8, kk + 4)]);
                }
                #pragma unroll
                for (int ni = 0; ni < 2; ni++) {
                    const int nr = wn * 16 + ni * 8 + g;
                    b[ni][0] = __float_as_uint(kch[aidx(nr, kk)]);
                    b[ni][1] = __float_as_uint(kch[aidx(nr, kk + 4)]);
                }
                #pragma unroll
                for (int mi = 0; mi < 2; mi++)
                    #pragma unroll
                    for (int ni = 0; ni < 2; ni++)
                        mma_tf32(sacc[mi][ni], a[mi], b[ni]);
            }
        }

        // ---------------- row-max partials (masked on diagonal) ----------------
        float pmax[4];
        #pragma unroll
        for (int mi = 0; mi < 2; mi++)
            #pragma unroll
            for (int h = 0; h < 2; h++) {
                const int rloc = wm * 32 + mi * 16 + h * 8 + g;
                float mx = -1e30f;
                #pragma unroll
                for (int ni = 0; ni < 2; ni++)
                    #pragma unroll
                    for (int p = 0; p < 2; p++) {
                        const int cloc = wn * 16 + ni * 8 + 2 * c + p;
                        const float v = sacc[mi][ni][h * 2 + p];
                        if (!diag || cloc <= rloc) mx = fmaxf(mx, v);
                    }
                pmax[mi * 2 + h] = mx;
            }
        #pragma unroll
        for (int i = 0; i < 4; i++) {
            pmax[i] = fmaxf(pmax[i], __shfl_xor_sync(0xffffffffu, pmax[i], 1));
            pmax[i] = fmaxf(pmax[i], __shfl_xor_sync(0xffffffffu, pmax[i], 2));
        }
        // lane (g,c) publishes row wm*32 + c*8 + g  (pmax index order: g, g+8, g+16, g+24)
        sBf[wn * 64 + wm * 32 + c * 8 + g] = pmax[c];
        __syncthreads();   // (a) — also retires sK for overwrite

        if (j < qt) { load_tile_a(sKs, Kg, (j + 1) * BC, t); cpa_commit(); }

        if (t < 64) {
            float mx = fmaxf(fmaxf(sBf[t], sBf[64 + t]), fmaxf(sBf[128 + t], sBf[192 + t]));
            const float mo = sM[t];
            const float mn = fmaxf(mo, mx);
            const float al = exp2f((mo - mn) * LOG2E);
            sAl[t] = al;
            sL[t] *= al;
            sM[t] = mn;
        }
        __syncthreads();   // (b)

        // ---------------- exp + P store + sum partials; O rescale ----------------
        float psum[4] = {0.f, 0.f, 0.f, 0.f};
        #pragma unroll
        for (int mi = 0; mi < 2; mi++)
            #pragma unroll
            for (int h = 0; h < 2; h++) {
                const int rloc = wm * 32 + mi * 16 + h * 8 + g;
                const float mn = sM[rloc];
                #pragma unroll
                for (int ni = 0; ni < 2; ni++) {
                    const int c0 = wn * 16 + ni * 8 + 2 * c;
                    #pragma unroll
                    for (int p = 0; p < 2; p++) {
                        const float v = sacc[mi][ni][h * 2 + p];
                        float e = (!diag || (c0 + p) <= rloc)
                                  ? exp2f((v - mn) * LOG2E) : 0.0f;
                        psum[mi * 2 + h] += e;
                        sP[aidx(rloc, c0 + p)] = f2tf32(e);
                    }
                }
            }
        #pragma unroll
        for (int i = 0; i < 4; i++) {
            psum[i] += __shfl_xor_sync(0xffffffffu, psum[i], 1);
            psum[i] += __shfl_xor_sync(0xffffffffu, psum[i], 2);
        }
        sBf[wn * 64 + wm * 32 + c * 8 + g] = psum[c];

        // rescale O accumulator (PV row layout: rows mi*16+g, +8)
        #pragma unroll
        for (int mi = 0; mi < 4; mi++) {
            const float a0 = sAl[mi * 16 + g];
            const float a1 = sAl[mi * 16 + 8 + g];
            #pragma unroll
            for (int ni = 0; ni < 4; ni++) {
                oacc[mi][ni][0] *= a0; oacc[mi][ni][1] *= a0;
                oacc[mi][ni][2] *= a1; oacc[mi][ni][3] *= a1;
            }
        }

        // V(j) ready (leave K(j+1) in flight if present)
        if (j < qt) asm volatile("cp.async.wait_group 1;");
        else        asm volatile("cp.async.wait_group 0;");
        __syncthreads();   // (c) — publishes P + sum partials + V visibility

        if (t < 64) sL[t] += sBf[t] + sBf[64 + t] + sBf[128 + t] + sBf[192 + t];

        // ---------------- PV: O += P @ V, warp owns dcols wid*32..+31 ----------------
        {
            const float* vch = sV + ((wid >> 1) << 12);
            const int nb = (wid & 1) * 32;
            #pragma unroll
            for (int kt = 0; kt < 8; kt++) {
                const int kr = (kt << 3) + c;
                uint32_t a[4][4], b[4][2];
                #pragma unroll
                for (int mi = 0; mi < 4; mi++) {
                    const int r = mi * 16 + g;
                    a[mi][0] = __float_as_uint(sP[aidx(r,     kr)]);
                    a[mi][1] = __float_as_uint(sP[aidx(r + 8, kr)]);
                    a[mi][2] = __float_as_uint(sP[aidx(r,     kr + 4)]);
                    a[mi][3] = __float_as_uint(sP[aidx(r + 8, kr + 4)]);
                }
                #pragma unroll
                for (int ni = 0; ni < 4; ni++) {
                    const int nc = nb + ni * 8 + g;
                    b[ni][0] = __float_as_uint(vch[vidx(kr,     nc)]);
                    b[ni][1] = __float_as_uint(vch[vidx(kr + 4, nc)]);
                }
                #pragma unroll
                for (int mi = 0; mi < 4; mi++)
                    #pragma unroll
                    for (int ni = 0; ni < 4; ni++)
                        mma_tf32(oacc[mi][ni], a[mi], b[ni]);
            }
        }
        __syncthreads();   // (d) — retires sP and sV

        if (j < qt) { load_tile_v(sVs, Vg, (j + 1) * BC, t); cpa_commit(); }
    }

    // ---------------- epilogue: O / l -> g_O [B,S,H,D] ----------------
    const int b = bh / H_;
    const int h = bh % H_;
    #pragma unroll
    for (int mi = 0; mi < 4; mi++) {
        const float inv0 = 1.0f / sL[mi * 16 + g];
        const float inv1 = 1.0f / sL[mi * 16 + 8 + g];
        const int r0 = q0 + mi * 16 + g;
        #pragma unroll
        for (int ni = 0; ni < 4; ni++) {
            const int col = wid * 32 + ni * 8 + 2 * c;
            const size_t o0 = ((size_t)b * S_ + r0) * (H_ * D_) + h * D_ + col;
            float2 lo = {oacc[mi][ni][0] * inv0, oacc[mi][ni][1] * inv0};
            float2 hi = {oacc[mi][ni][2] * inv1, oacc[mi][ni][3] * inv1};
            *(float2*)(g_O + o0)                          = lo;
            *(float2*)(g_O + o0 + (size_t)8 * (H_ * D_))  = hi;
        }
    }
}

// ===========================================================================
//            gemm_cp (proven R6 engine) for proj / out kernels
// ===========================================================================
#define SA_STRIDE 20
#define SBN_STRIDE 136

template <bool TB, bool CVTL, bool CVTS>
__device__ __forceinline__ void gemm_cp(const float* __restrict__ A,
                                        const float* __restrict__ Bm,
                                        float* __restrict__ C,
                                        int K, int lda, int ldb, int ldc,
                                        float scale, int mtile)
{
    __shared__ float As[2][128 * SA_STRIDE];
    __shared__ float Bs[2][128 * SA_STRIDE];

    const int t    = threadIdx.x;
    const int lane = t & 31;
    const int wid  = t >> 5;
    const int wm   = wid >> 2;
    const int wn   = wid & 3;
    const int g    = lane >> 2;
    const int c    = lane & 3;
    const int m0   = mtile * 128;
    const int n0   = blockIdx.y * 128;

    const uint32_t sA0 = (uint32_t)__cvta_generic_to_shared(&As[0][0]);
    const uint32_t sA1 = (uint32_t)__cvta_generic_to_shared(&As[1][0]);
    const uint32_t sB0 = (uint32_t)__cvta_generic_to_shared(&Bs[0][0]);
    const uint32_t sB1 = (uint32_t)__cvta_generic_to_shared(&Bs[1][0]);

    const int aRow0 = t >> 2,         aC0 = (t & 3) * 4;
    const int aRow1 = (t + 256) >> 2, aC1 = aC0;
    const int bK0 = t >> 5,           bN0 = (t & 31) * 4;
    const int bK1 = (t + 256) >> 5,   bN1 = bN0;

    auto issue_stage = [&](int k0, int buf) {
        const uint32_t sa = buf ? sA1 : sA0;
        const uint32_t sb = buf ? sB1 : sB0;
        cpa16(sa + (aRow0 * SA_STRIDE + aC0) * 4, A + (size_t)(m0 + aRow0) * lda + k0 + aC0);
        cpa16(sa + (aRow1 * SA_STRIDE + aC1) * 4, A + (size_t)(m0 + aRow1) * lda + k0 + aC1);
        if (TB) {
            cpa16(sb + (aRow0 * SA_STRIDE + aC0) * 4, Bm + (size_t)(n0 + aRow0) * ldb + k0 + aC0);
            cpa16(sb + (aRow1 * SA_STRIDE + aC1) * 4, Bm + (size_t)(n0 + aRow1) * ldb + k0 + aC1);
        } else {
            cpa16(sb + (bK0 * SBN_STRIDE + bN0) * 4, Bm + (size_t)(k0 + bK0) * ldb + n0 + bN0);
            cpa16(sb + (bK1 * SBN_STRIDE + bN1) * 4, Bm + (size_t)(k0 + bK1) * ldb + n0 + bN1);
        }
        cpa_commit();
    };

    float acc[4][4][4] = {};

    auto ldval = [&](const float* p) -> uint32_t {
        float v = *p;
        if (CVTL) v = f2tf32(v);
        return __float_as_uint(v);
    };

    auto compute_stage = [&](int buf) {
        const float* as = As[buf];
        const float* bs = Bs[buf];
        #pragma unroll
        for (int kt = 0; kt < 2; kt++) {
            uint32_t a[4][4], b[4][2];
            #pragma unroll
            for (int i = 0; i < 4; i++) {
                const int row = wm * 64 + i * 16 + g;
                const int base = row * SA_STRIDE + kt * 8 + c;
                a[i][0] = ldval(as + base);
                a[i][1] = ldval(as + base + 8 * SA_STRIDE);
                a[i][2] = ldval(as + base + 4);
                a[i][3] = ldval(as + base + 8 * SA_STRIDE + 4);
            }
            #pragma unroll
            for (int j = 0; j < 4; j++) {
                if (TB) {
                    const int base = (wn * 32 + j * 8 + g) * SA_STRIDE + kt * 8 + c;
                    b[j][0] = ldval(bs + base);
                    b[j][1] = ldval(bs + base + 4);
                } else {
                    const int base = (kt * 8 + c) * SBN_STRIDE + wn * 32 + j * 8 + g;
                    b[j][0] = ldval(bs + base);
                    b[j][1] = ldval(bs + base + 4 * SBN_STRIDE);
                }
            }
            #pragma unroll
            for (int i = 0; i < 4; i++)
                #pragma unroll
                for (int j = 0; j < 4; j++)
                    mma_tf32(acc[i][j], a[i], b[j]);
        }
    };

    const int KS = K >> 4;
    issue_stage(0, 0);
    for (int ks = 0; ks < KS; ks++) {
        if (ks + 1 < KS) {
            issue_stage((ks + 1) << 4, (ks + 1) & 1);
            asm volatile("cp.async.wait_group 1;");
        } else {
            asm volatile("cp.async.wait_group 0;");
        }
        __syncthreads();
        compute_stage(ks & 1);
        __syncthreads();
    }

    #pragma unroll
    for (int i = 0; i < 4; i++) {
        #pragma unroll
        for (int j = 0; j < 4; j++) {
            const int row = m0 + wm * 64 + i * 16 + g;
            const int col = n0 + wn * 32 + j * 8 + c * 2;
            float2 lo = {acc[i][j][0] * scale, acc[i][j][1] * scale};
            float2 hi = {acc[i][j][2] * scale, acc[i][j][3] * scale};
            if (CVTS) {
                lo.x = f2tf32(lo.x); lo.y = f2tf32(lo.y);
                hi.x = f2tf32(hi.x); hi.y = f2tf32(hi.y);
            }
            *(float2*)(C + (size_t)row * ldc + col)       = lo;
            *(float2*)(C + (size_t)(row + 8) * ldc + col) = hi;
        }
    }
}

// Q/K/V projections; Q gets 1/sqrt(D)=1/16 folded in (power of 2 -> exact)
__global__ __launch_bounds__(256, 2) void proj_kernel(const float* __restrict__ x,
                                                      const float* __restrict__ wQ,
                                                      const float* __restrict__ wK,
                                                      const float* __restrict__ wV)
{
    const int z     = blockIdx.z;
    const int which = z / (B_ * H_);
    const int bh    = z % (B_ * H_);
    const int b     = bh / H_;
    const int h     = bh % H_;

    const float* A = x + (size_t)b * S_ * D_;
    const float* W = (which == 0 ? wQ : which == 1 ? wK : wV) + (size_t)h * D_ * D_;
    float* C = (which == 0 ? g_Q : which == 1 ? g_K : g_V) + (size_t)bh * S_ * D_;
    const float scale = (which == 0) ? 0.0625f : 1.0f;

    gemm_cp<false, true, true>(A, W, C, D_, D_, D_, D_, scale, blockIdx.x);
}

__global__ __launch_bounds__(256, 2) void out_kernel(const float* __restrict__ wO,
                                                     float* __restrict__ out)
{
    gemm_cp<false, true, false>(g_O, wO, out, H_ * D_, H_ * D_, D_, D_, 1.0f, blockIdx.x);
}

// ---------------------------------------------------------------------------
extern "C" void kernel_launch(void* const* d_in, const int* in_sizes, int n_in,
                              void* d_out, int out_size)
{
    const float* x  = (const float*)d_in[0];
    // d_in[1] = timestamp (dead code in reference)
    const float* wQ = (const float*)d_in[2];
    const float* wK = (const float*)d_in[3];
    const float* wV = (const float*)d_in[4];
    const float* wO = (const float*)d_in[5];
    // d_in[6] = theta (dead code)
    float* out = (float*)d_out;

    static bool attr_done = false;
    if (!attr_done) {
        cudaFuncSetAttribute(flash_kernel,
                             cudaFuncAttributeMaxDynamicSharedMemorySize,
                             FLASH_SMEM_BYTES);
        attr_done = true;
    }

    dim3 blk(256);
    proj_kernel<<<dim3(S_ / 128, D_ / 128, 3 * B_ * H_), blk>>>(x, wQ, wK, wV);
    flash_kernel<<<dim3(S_ / BR, B_ * H_), blk, FLASH_SMEM_BYTES>>>();
    out_kernel<<<dim3(B_ * S_ / 128, D_ / 128, 1), blk>>>(wO, out);
}

// round 8
// speedup vs baseline: 1.3618x; 1.3618x over previous
#include <cuda_runtime.h>
#include <cuda_bf16.h>
#include <cstdint>

#define B_ 2
#define S_ 2048
#define D_ 256
#define H_ 8

// Scratch (no allocations allowed -> static device globals)
__device__ float g_Q[(size_t)B_ * H_ * S_ * D_];   // tf32-rounded
__device__ float g_K[(size_t)B_ * H_ * S_ * D_];   // tf32-rounded
__device__ float g_V[(size_t)B_ * H_ * S_ * D_];   // tf32-rounded
__device__ float g_P[(size_t)B_ * H_ * S_ * S_];   // scores (raw) -> probs (tf32-rounded)
__device__ float g_O[(size_t)B_ * S_ * H_ * D_];   // raw fp32 [B,S,H,D]

// round-to-nearest tf32 (unbiased)
__device__ __forceinline__ float f2tf32(float x) {
    uint32_t r;
    asm("cvt.rna.tf32.f32 %0, %1;" : "=r"(r) : "f"(x));
    return __uint_as_float(r);
}

__device__ __forceinline__ void mma_tf32(float* c, const uint32_t* a, const uint32_t* b) {
    asm volatile(
        "mma.sync.aligned.m16n8k8.row.col.f32.tf32.tf32.f32 "
        "{%0,%1,%2,%3}, {%4,%5,%6,%7}, {%8,%9}, {%0,%1,%2,%3};"
        : "+f"(c[0]), "+f"(c[1]), "+f"(c[2]), "+f"(c[3])
        : "r"(a[0]), "r"(a[1]), "r"(a[2]), "r"(a[3]), "r"(b[0]), "r"(b[1]));
}

__device__ __forceinline__ void cpa16(uint32_t dst, const void* src) {
    asm volatile("cp.async.cg.shared.global [%0], [%1], 16;" :: "r"(dst), "l"(src));
}
__device__ __forceinline__ void cpa_commit() { asm volatile("cp.async.commit_group;"); }

#define SA_STRIDE 20     // 16 data + 4 pad floats: g*20+c bijective mod 32 banks
#define SBN_STRIDE 136   // 128 data + 8 pad: c*8+g bijective mod 32 banks
#define STAGES 4
#define STAGE_FLOATS 5120           // 2560 (A) + 2560 (B)
#define GEMM_SMEM_BYTES (STAGES * STAGE_FLOATS * 4)   // 80 KB

// ---------------------------------------------------------------------------
// 128x128 CTA tile tf32 tensor-core GEMM, 256 threads = 8 warps (2m x 4n),
// each warp 64x32 via m16n8k8. BK=16, 4-stage circular cp.async pipeline in
// dynamic smem, ONE barrier per stage, conflict-free padded strides.
// TB=false: C = A[M,K] * B[K,N] ; TB=true: C = A[M,K] * B[N,K]^T
// CVTL: round loads to tf32 (external fp32 inputs). CVTS: round stores.
// ---------------------------------------------------------------------------
template <bool TB, bool CVTL, bool CVTS>
__device__ __forceinline__ void gemm_cp(const float* __restrict__ A,
                                        const float* __restrict__ Bm,
                                        float* __restrict__ C,
                                        int K, int lda, int ldb, int ldc,
                                        float scale, int mtile)
{
    extern __shared__ float smem[];

    const int t    = threadIdx.x;
    const int lane = t & 31;
    const int wid  = t >> 5;
    const int wm   = wid >> 2;      // 0..1
    const int wn   = wid & 3;       // 0..3
    const int g    = lane >> 2;     // 0..7
    const int c    = lane & 3;      // 0..3
    const int m0   = mtile * 128;
    const int n0   = blockIdx.y * 128;

    const uint32_t sbase = (uint32_t)__cvta_generic_to_shared(smem);

    // loader indices: 2 x 16B chunks for A, 2 for B
    const int aRow0 = t >> 2,         aC0 = (t & 3) * 4;
    const int aRow1 = (t + 256) >> 2, aC1 = aC0;
    const int bK0 = t >> 5,           bN0 = (t & 31) * 4;
    const int bK1 = (t + 256) >> 5,   bN1 = bN0;

    // issue one BK=16 stage into circular buffer s; ALWAYS commit (uniform
    // group accounting so wait_group 2 retires exactly stage ks, incl. tail)
    auto issue_stage = [&](int k0, int s, bool pred) {
        if (pred) {
            const uint32_t sa = sbase + (uint32_t)(s * STAGE_FLOATS) * 4u;
            const uint32_t sb = sa + 2560u * 4u;
            cpa16(sa + (aRow0 * SA_STRIDE + aC0) * 4, A + (size_t)(m0 + aRow0) * lda + k0 + aC0);
            cpa16(sa + (aRow1 * SA_STRIDE + aC1) * 4, A + (size_t)(m0 + aRow1) * lda + k0 + aC1);
            if (TB) {
                cpa16(sb + (aRow0 * SA_STRIDE + aC0) * 4, Bm + (size_t)(n0 + aRow0) * ldb + k0 + aC0);
                cpa16(sb + (aRow1 * SA_STRIDE + aC1) * 4, Bm + (size_t)(n0 + aRow1) * ldb + k0 + aC1);
            } else {
                cpa16(sb + (bK0 * SBN_STRIDE + bN0) * 4, Bm + (size_t)(k0 + bK0) * ldb + n0 + bN0);
                cpa16(sb + (bK1 * SBN_STRIDE + bN1) * 4, Bm + (size_t)(k0 + bK1) * ldb + n0 + bN1);
            }
        }
        cpa_commit();
    };

    float acc[4][4][4] = {};

    auto ldval = [&](const float* p) -> uint32_t {
        float v = *p;
        if (CVTL) v = f2tf32(v);
        return __float_as_uint(v);
    };

    auto compute_stage = [&](int s) {
        const float* as = smem + s * STAGE_FLOATS;
        const float* bs = as + 2560;
        #pragma unroll
        for (int kt = 0; kt < 2; kt++) {
            uint32_t a[4][4], b[4][2];
            #pragma unroll
            for (int i = 0; i < 4; i++) {
                const int row = wm * 64 + i * 16 + g;
                const int base = row * SA_STRIDE + kt * 8 + c;
                a[i][0] = ldval(as + base);
                a[i][1] = ldval(as + base + 8 * SA_STRIDE);
                a[i][2] = ldval(as + base + 4);
                a[i][3] = ldval(as + base + 8 * SA_STRIDE + 4);
            }
            #pragma unroll
            for (int j = 0; j < 4; j++) {
                if (TB) {
                    const int base = (wn * 32 + j * 8 + g) * SA_STRIDE + kt * 8 + c;
                    b[j][0] = ldval(bs + base);
                    b[j][1] = ldval(bs + base + 4);
                } else {
                    const int base = (kt * 8 + c) * SBN_STRIDE + wn * 32 + j * 8 + g;
                    b[j][0] = ldval(bs + base);
                    b[j][1] = ldval(bs + base + 4 * SBN_STRIDE);
                }
            }
            #pragma unroll
            for (int i = 0; i < 4; i++)
                #pragma unroll
                for (int j = 0; j < 4; j++)
                    mma_tf32(acc[i][j], a[i], b[j]);
        }
    };

    const int KS = K >> 4;
    // prologue: stages 0,1,2 (predicated; commits always happen)
    issue_stage(0,  0, true);
    issue_stage(16, 1, 1 < KS);
    issue_stage(32, 2, 2 < KS);

    for (int ks = 0; ks < KS; ks++) {
        // groups committed so far: ks+3 (indices 0..ks+2); keep <=2 younger
        // outstanding -> group ks (stage ks) is complete.
        asm volatile("cp.async.wait_group 2;");
        __syncthreads();
        // overwrites buffer (ks-1)%4: all threads finished computing it
        // before the barrier above.
        issue_stage((ks + 3) << 4, (ks + 3) & 3, ks + 3 < KS);
        compute_stage(ks & 3);
    }

    // Epilogue: m16n8 c-frag -> (g,2c),(g,2c+1) and (g+8,...)
    #pragma unroll
    for (int i = 0; i < 4; i++) {
        #pragma unroll
        for (int j = 0; j < 4; j++) {
            const int row = m0 + wm * 64 + i * 16 + g;
            const int col = n0 + wn * 32 + j * 8 + c * 2;
            float2 lo = {acc[i][j][0] * scale, acc[i][j][1] * scale};
            float2 hi = {acc[i][j][2] * scale, acc[i][j][3] * scale};
            if (CVTS) {
                lo.x = f2tf32(lo.x); lo.y = f2tf32(lo.y);
                hi.x = f2tf32(hi.x); hi.y = f2tf32(hi.y);
            }
            *(float2*)(C + (size_t)row * ldc + col)       = lo;
            *(float2*)(C + (size_t)(row + 8) * ldc + col) = hi;
        }
    }
}

// ---------------------------------------------------------------------------
// 1) Q/K/V projections (external fp32 in -> tf32-rounded out)
// ---------------------------------------------------------------------------
__global__ __launch_bounds__(256, 2) void proj_kernel(const float* __restrict__ x,
                                                      const float* __restrict__ wQ,
                                                      const float* __restrict__ wK,
                                                      const float* __restrict__ wV)
{
    const int z     = blockIdx.z;
    const int which = z / (B_ * H_);
    const int bh    = z % (B_ * H_);
    const int b     = bh / H_;
    const int h     = bh % H_;

    const float* A = x + (size_t)b * S_ * D_;
    const float* W = (which == 0 ? wQ : which == 1 ? wK : wV) + (size_t)h * D_ * D_;
    float* C = (which == 0 ? g_Q : which == 1 ? g_K : g_V) + (size_t)bh * S_ * D_;

    gemm_cp<false, true, true>(A, W, C, D_, D_, D_, D_, 1.0f, blockIdx.x);
}

// ---------------------------------------------------------------------------
// 2) Scores = Q @ K^T / sqrt(D); inputs pre-rounded, raw fp32 scores out
// ---------------------------------------------------------------------------
__global__ __launch_bounds__(256, 2) void qk_kernel()
{
    if (blockIdx.y > blockIdx.x) return;
    const int bh = blockIdx.z;
    const float* A  = g_Q + (size_t)bh * S_ * D_;
    const float* Bm = g_K + (size_t)bh * S_ * D_;
    float* C = g_P + (size_t)bh * S_ * S_;
    gemm_cp<true, false, false>(A, Bm, C, D_, D_, D_, S_, 0.0625f, blockIdx.x);
}

// ---------------------------------------------------------------------------
// 3) Causal softmax; writes tf32-rounded probs, zero-fills j>i
// ---------------------------------------------------------------------------
__global__ void softmax_kernel()
{
    const int i  = blockIdx.x;
    const int bh = blockIdx.y;
    float* row = g_P + ((size_t)bh * S_ + i) * S_;
    const int len = i + 1;
    const int t = threadIdx.x;
    __shared__ float red[8];

    float m = -3.402823e38f;
    for (int j = t; j < len; j += 256) m = fmaxf(m, row[j]);
    #pragma unroll
    for (int o = 16; o; o >>= 1) m = fmaxf(m, __shfl_xor_sync(0xffffffffu, m, o));
    if ((t & 31) == 0) red[t >> 5] = m;
    __syncthreads();
    m = red[0];
    #pragma unroll
    for (int w = 1; w < 8; w++) m = fmaxf(m, red[w]);
    __syncthreads();

    float s = 0.0f;
    for (int j = t; j < len; j += 256) {
        float e = __expf(row[j] - m);
        row[j] = e;
        s += e;
    }
    #pragma unroll
    for (int o = 16; o; o >>= 1) s += __shfl_xor_sync(0xffffffffu, s, o);
    if ((t & 31) == 0) red[t >> 5] = s;
    __syncthreads();
    float tot = red[0];
    #pragma unroll
    for (int w = 1; w < 8; w++) tot += red[w];
    const float inv = 1.0f / tot;

    for (int j = t; j < len; j += 256) row[j] = f2tf32(row[j] * inv);
    for (int j = len + t; j < S_; j += 256) row[j] = 0.0f;
}

// ---------------------------------------------------------------------------
// 4) O = P @ V, K truncated at causal boundary; heavy tiles first
// ---------------------------------------------------------------------------
__global__ __launch_bounds__(256, 2) void pv_kernel()
{
    const int bh = blockIdx.z;
    const int b  = bh / H_;
    const int h  = bh % H_;
    const int mtile = gridDim.x - 1 - blockIdx.x;
    const int Keff = (mtile + 1) * 128;
    const float* A  = g_P + (size_t)bh * S_ * S_;
    const float* Bm = g_V + (size_t)bh * S_ * D_;
    float* C = g_O + (size_t)b * S_ * H_ * D_ + (size_t)h * D_;
    gemm_cp<false, false, false>(A, Bm, C, Keff, S_, D_, H_ * D_, 1.0f, mtile);
}

// ---------------------------------------------------------------------------
// 5) out[B*S, D] = g_O[B*S, H*D] @ wO[H*D, D]  (raw fp32 inputs -> cvt on load)
// ---------------------------------------------------------------------------
__global__ __launch_bounds__(256, 2) void out_kernel(const float* __restrict__ wO,
                                                     float* __restrict__ out)
{
    gemm_cp<false, true, false>(g_O, wO, out, H_ * D_, H_ * D_, D_, D_, 1.0f, blockIdx.x);
}

// ---------------------------------------------------------------------------
extern "C" void kernel_launch(void* const* d_in, const int* in_sizes, int n_in,
                              void* d_out, int out_size)
{
    const float* x  = (const float*)d_in[0];
    // d_in[1] = timestamp (dead code in reference)
    const float* wQ = (const float*)d_in[2];
    const float* wK = (const float*)d_in[3];
    const float* wV = (const float*)d_in[4];
    const float* wO = (const float*)d_in[5];
    // d_in[6] = theta (dead code)
    float* out = (float*)d_out;

    // host-side attribute set (idempotent; not a graph node)
    cudaFuncSetAttribute(proj_kernel, cudaFuncAttributeMaxDynamicSharedMemorySize, GEMM_SMEM_BYTES);
    cudaFuncSetAttribute(qk_kernel,   cudaFuncAttributeMaxDynamicSharedMemorySize, GEMM_SMEM_BYTES);
    cudaFuncSetAttribute(pv_kernel,   cudaFuncAttributeMaxDynamicSharedMemorySize, GEMM_SMEM_BYTES);
    cudaFuncSetAttribute(out_kernel,  cudaFuncAttributeMaxDynamicSharedMemorySize, GEMM_SMEM_BYTES);

    dim3 blk(256);
    proj_kernel<<<dim3(S_ / 128, D_ / 128, 3 * B_ * H_), blk, GEMM_SMEM_BYTES>>>(x, wQ, wK, wV);
    qk_kernel<<<dim3(S_ / 128, S_ / 128, B_ * H_), blk, GEMM_SMEM_BYTES>>>();
    softmax_kernel<<<dim3(S_, B_ * H_), blk>>>();
    pv_kernel<<<dim3(S_ / 128, D_ / 128, B_ * H_), blk, GEMM_SMEM_BYTES>>>();
    out_kernel<<<dim3(B_ * S_ / 128, D_ / 128, 1), blk, GEMM_SMEM_BYTES>>>(wO, out);
}